// round 5
// baseline (speedup 1.0000x reference)
#include <cuda_runtime.h>
#include <cstdint>

#define N_NODES 100000
#define E_MAX   1700000
#define F_IN    128
#define F_HID   64
#define F_OUT   32
#define SCAN_T  1024

// Scratch (no allocations allowed). Referenced ONLY from device code.
__device__ float g_h[N_NODES * F_HID];     // h1 = x@W1
__device__ float g_h2[N_NODES * F_HID];    // relu(gcn1)
__device__ float g_agg[N_NODES * F_HID];   // hagg2 (pre-output-GEMM)
__device__ float g_dinv[N_NODES];          // 1/sqrt(deg)
__device__ int   g_count[N_NODES];         // in-degree (excl. self-loop)
__device__ int   g_cursor[N_NODES];        // fill cursors
__device__ int   g_rowstart[N_NODES + 1];  // CSR row offsets (by dst)
__device__ int   g_adj[E_MAX];             // src ids grouped by dst
__device__ int   g_is32;                   // 1 if edge_index is int32

// ---------------------------------------------------------------------------
// index readers (uniform branch on detected dtype)
// ---------------------------------------------------------------------------
__device__ __forceinline__ int read_idx(const void* ei, int E, int row, int e,
                                        int is32) {
    if (is32)  return ((const int*)ei)[(size_t)row * E + e];
    else       return (int)((const long long*)ei)[(size_t)row * E + e];
}

// ---------------------------------------------------------------------------
// 1. init: zero counts + cursors + dtype flag
// ---------------------------------------------------------------------------
__global__ void init_kernel() {
    int i = blockIdx.x * blockDim.x + threadIdx.x;
    if (i < N_NODES) { g_count[i] = 0; g_cursor[i] = 0; }
    if (i == 0) g_is32 = 0;
}

// ---------------------------------------------------------------------------
// 1b. dtype detect: int64 node ids (< 1e5) have zero high-32 in every word;
//     packed int32 pairs have nonzero high half whenever idx[2t+1] != 0.
// ---------------------------------------------------------------------------
__global__ void detect_kernel(const unsigned long long* __restrict__ ei, int E) {
    int t = blockIdx.x * blockDim.x + threadIdx.x;
    int limit = (E < 2048) ? E : 2048;   // words fully inside row 0 either way
    if (t < limit) {
        if (ei[t] > 0xFFFFFFFFULL) atomicExch(&g_is32, 1);
    }
}

// ---------------------------------------------------------------------------
// 2. histogram of dst (scalar int atomics only)
// ---------------------------------------------------------------------------
__global__ void hist_kernel(const void* __restrict__ ei, int E) {
    int e = blockIdx.x * blockDim.x + threadIdx.x;
    if (e >= E) return;
    int d = read_idx(ei, E, 1, e, g_is32);
    atomicAdd(&g_count[d], 1);
}

// ---------------------------------------------------------------------------
// 3. exclusive scan -> row_start; dinv = rsqrt(count + 1). Single block.
// ---------------------------------------------------------------------------
__global__ void scan_kernel() {
    __shared__ int part[SCAN_T];
    const int C = (N_NODES + SCAN_T - 1) / SCAN_T;
    int t = threadIdx.x;
    int base = t * C;

    int sum = 0;
    for (int i = 0; i < C; i++) {
        int idx = base + i;
        if (idx < N_NODES) sum += g_count[idx];
    }
    part[t] = sum;
    __syncthreads();

    for (int off = 1; off < SCAN_T; off <<= 1) {
        int v = (t >= off) ? part[t - off] : 0;
        __syncthreads();
        part[t] += v;
        __syncthreads();
    }

    int running = part[t] - sum;
    for (int i = 0; i < C; i++) {
        int idx = base + i;
        if (idx < N_NODES) {
            int c = g_count[idx];
            g_rowstart[idx] = running;
            g_dinv[idx] = rsqrtf((float)c + 1.0f);
            running += c;
        }
    }
    if (t == SCAN_T - 1) g_rowstart[N_NODES] = part[SCAN_T - 1];
}

// ---------------------------------------------------------------------------
// 4. fill adjacency (src ids grouped by dst; order irrelevant)
// ---------------------------------------------------------------------------
__global__ void fill_kernel(const void* __restrict__ ei, int E) {
    int e = blockIdx.x * blockDim.x + threadIdx.x;
    if (e >= E) return;
    int is32 = g_is32;
    int sidx = read_idx(ei, E, 0, e, is32);
    int d    = read_idx(ei, E, 1, e, is32);
    int pos = atomicAdd(&g_cursor[d], 1);
    g_adj[g_rowstart[d] + pos] = sidx;
}

// ---------------------------------------------------------------------------
// 5. g_h = x @ W1   (N x 128) @ (128 x 64)
// ---------------------------------------------------------------------------
__global__ void gemm1_kernel(const float* __restrict__ x,
                             const float* __restrict__ W1) {
    __shared__ float Ws[F_IN * F_HID];   // 32 KB
    __shared__ float xs[16][F_IN];       // 8 KB

    int tid = threadIdx.x;               // 0..255
    for (int i = tid; i < F_IN * F_HID; i += 256) Ws[i] = W1[i];

    int row0 = blockIdx.x * 16;
    for (int i = tid; i < 16 * F_IN; i += 256) {
        int r = i >> 7, k = i & 127;
        int row = row0 + r;
        xs[r][k] = (row < N_NODES) ? x[(size_t)row * F_IN + k] : 0.0f;
    }
    __syncthreads();

    int col = tid & 63;
    int rg  = tid >> 6;
    float acc0 = 0.f, acc1 = 0.f, acc2 = 0.f, acc3 = 0.f;
    int rbase = rg * 4;
#pragma unroll
    for (int k = 0; k < F_IN; k++) {
        float w = Ws[k * F_HID + col];
        acc0 = fmaf(xs[rbase + 0][k], w, acc0);
        acc1 = fmaf(xs[rbase + 1][k], w, acc1);
        acc2 = fmaf(xs[rbase + 2][k], w, acc2);
        acc3 = fmaf(xs[rbase + 3][k], w, acc3);
    }
    int row = row0 + rbase;
    if (row + 0 < N_NODES) g_h[(size_t)(row + 0) * F_HID + col] = acc0;
    if (row + 1 < N_NODES) g_h[(size_t)(row + 1) * F_HID + col] = acc1;
    if (row + 2 < N_NODES) g_h[(size_t)(row + 2) * F_HID + col] = acc2;
    if (row + 3 < N_NODES) g_h[(size_t)(row + 3) * F_HID + col] = acc3;
}

// ---------------------------------------------------------------------------
// 6/7. aggregate: one warp per node. Lane l accumulates features 2l, 2l+1.
//      out[d] = sum_{s in adj(d)} dinv[s]*dinv[d]*in[s] + dinv[d]^2*in[d]
// ---------------------------------------------------------------------------
template <bool PASS1>
__global__ void agg_kernel(const float* __restrict__ b1) {
    const float* in  = PASS1 ? g_h  : g_h2;
    float*       out = PASS1 ? g_h2 : g_agg;

    int warp = threadIdx.x >> 5;
    int lane = threadIdx.x & 31;
    int node = blockIdx.x * 8 + warp;     // 256 threads = 8 warps
    if (node >= N_NODES) return;

    float di = g_dinv[node];
    float2 v = *reinterpret_cast<const float2*>(&in[(size_t)node * F_HID + lane * 2]);
    float accx = di * di * v.x;
    float accy = di * di * v.y;

    int beg = g_rowstart[node];
    int end = g_rowstart[node + 1];

    int j = beg;
    for (; j + 1 < end; j += 2) {
        int s0 = g_adj[j];
        int s1 = g_adj[j + 1];
        float c0 = g_dinv[s0] * di;
        float c1 = g_dinv[s1] * di;
        float2 h0 = *reinterpret_cast<const float2*>(&in[(size_t)s0 * F_HID + lane * 2]);
        float2 h1 = *reinterpret_cast<const float2*>(&in[(size_t)s1 * F_HID + lane * 2]);
        accx = fmaf(c0, h0.x, accx);
        accy = fmaf(c0, h0.y, accy);
        accx = fmaf(c1, h1.x, accx);
        accy = fmaf(c1, h1.y, accy);
    }
    if (j < end) {
        int s = g_adj[j];
        float c = g_dinv[s] * di;
        float2 hv = *reinterpret_cast<const float2*>(&in[(size_t)s * F_HID + lane * 2]);
        accx = fmaf(c, hv.x, accx);
        accy = fmaf(c, hv.y, accy);
    }

    if (PASS1) {
        accx += b1[lane * 2 + 0];
        accy += b1[lane * 2 + 1];
        accx = accx > 0.f ? accx : 0.f;
        accy = accy > 0.f ? accy : 0.f;
    }
    *reinterpret_cast<float2*>(&out[(size_t)node * F_HID + lane * 2]) =
        make_float2(accx, accy);
}

// ---------------------------------------------------------------------------
// 8. out GEMMs: mu = g_agg@W_mu + b_mu; ls = g_agg@W_ls + b_ls
// ---------------------------------------------------------------------------
__global__ void out_kernel(const float* __restrict__ Wmu,
                           const float* __restrict__ bmu,
                           const float* __restrict__ Wls,
                           const float* __restrict__ bls,
                           float* __restrict__ out) {
    __shared__ float Wm[F_HID * F_OUT];
    __shared__ float Wl[F_HID * F_OUT];
    __shared__ float hs[8][F_HID];

    int tid = threadIdx.x;  // 0..255
    for (int i = tid; i < F_HID * F_OUT; i += 256) { Wm[i] = Wmu[i]; Wl[i] = Wls[i]; }

    int node0 = blockIdx.x * 8;
    for (int i = tid; i < 8 * F_HID; i += 256) {
        int r = i >> 6, f = i & 63;
        int node = node0 + r;
        if (node < N_NODES) hs[r][f] = g_agg[(size_t)node * F_HID + f];
    }
    __syncthreads();

    int warp = tid >> 5, lane = tid & 31;
    int node = node0 + warp;
    if (node >= N_NODES) return;

    float am = bmu[lane];
    float al = bls[lane];
#pragma unroll
    for (int f = 0; f < F_HID; f++) {
        float hv = hs[warp][f];
        am = fmaf(hv, Wm[f * F_OUT + lane], am);
        al = fmaf(hv, Wl[f * F_OUT + lane], al);
    }
    out[(size_t)node * F_OUT + lane] = am;
    out[(size_t)N_NODES * F_OUT + (size_t)node * F_OUT + lane] = al;
}

// ---------------------------------------------------------------------------
// launch — everything on cudaStreamPerThread so graph capture records it
// ---------------------------------------------------------------------------
extern "C" void kernel_launch(void* const* d_in, const int* in_sizes, int n_in,
                              void* d_out, int out_size) {
    const float* x   = (const float*)d_in[0];
    const void*  ei  = d_in[1];                    // [2, E], int32 OR int64
    const float* W1  = (const float*)d_in[2];
    const float* b1  = (const float*)d_in[3];
    const float* Wmu = (const float*)d_in[4];
    const float* bmu = (const float*)d_in[5];
    const float* Wls = (const float*)d_in[6];
    const float* bls = (const float*)d_in[7];
    float*       out = (float*)d_out;

    const int E = in_sizes[1] / 2;
    const int T = 256;
    cudaStream_t s = cudaStreamPerThread;

    init_kernel<<<(N_NODES + T - 1) / T, T, 0, s>>>();
    detect_kernel<<<8, T, 0, s>>>((const unsigned long long*)ei, E);
    hist_kernel<<<(E + T - 1) / T, T, 0, s>>>(ei, E);
    scan_kernel<<<1, SCAN_T, 0, s>>>();
    fill_kernel<<<(E + T - 1) / T, T, 0, s>>>(ei, E);
    gemm1_kernel<<<(N_NODES + 15) / 16, T, 0, s>>>(x, W1);
    agg_kernel<true ><<<(N_NODES + 7) / 8, T, 0, s>>>(b1);
    agg_kernel<false><<<(N_NODES + 7) / 8, T, 0, s>>>(b1);
    out_kernel<<<(N_NODES + 7) / 8, T, 0, s>>>(Wmu, bmu, Wls, bls, out);
}

// round 6
// speedup vs baseline: 1.4819x; 1.4819x over previous
#include <cuda_runtime.h>
#include <cstdint>

#define N_NODES 100000
#define E_MAX   1700000
#define F_IN    128
#define F_HID   64
#define F_OUT   32
#define SCAN_TPB 1024
#define SCAN_NB  ((N_NODES + SCAN_TPB - 1) / SCAN_TPB)   // 98

// Scratch (no allocations allowed). Referenced ONLY from device code.
__device__ float g_h[N_NODES * F_HID];     // h1 = x@W1
__device__ float g_h2[N_NODES * F_HID];    // relu(gcn1)
__device__ float g_agg[N_NODES * F_HID];   // hagg2 (pre-output-GEMM)
__device__ float g_dinv[N_NODES];          // 1/sqrt(deg)
__device__ int   g_count[N_NODES];         // in-degree (excl. self-loop)
__device__ int   g_cursor[N_NODES];        // fill cursors
__device__ int   g_rowstart[N_NODES + 1];  // CSR row offsets (by dst)
__device__ int   g_adj[E_MAX];             // src ids grouped by dst
__device__ int   g_partial[SCAN_NB];       // per-block sums for scan
__device__ int   g_is32;                   // 1 if edge_index is int32

// ---------------------------------------------------------------------------
// index readers (uniform branch on detected dtype)
// ---------------------------------------------------------------------------
__device__ __forceinline__ int read_idx(const void* ei, int E, int row, int e,
                                        int is32) {
    if (is32)  return ((const int*)ei)[(size_t)row * E + e];
    else       return (int)((const long long*)ei)[(size_t)row * E + e];
}

// ---------------------------------------------------------------------------
// 1. init: zero counts + cursors + dtype flag
// ---------------------------------------------------------------------------
__global__ void init_kernel() {
    int i = blockIdx.x * blockDim.x + threadIdx.x;
    if (i < N_NODES) { g_count[i] = 0; g_cursor[i] = 0; }
    if (i == 0) g_is32 = 0;
}

// ---------------------------------------------------------------------------
// 1b. dtype detect: int64 node ids (< 1e5) have zero high-32 in every word;
//     packed int32 pairs have nonzero high half whenever idx[2t+1] != 0.
// ---------------------------------------------------------------------------
__global__ void detect_kernel(const unsigned long long* __restrict__ ei, int E) {
    int t = blockIdx.x * blockDim.x + threadIdx.x;
    int limit = (E < 2048) ? E : 2048;   // words fully inside row 0 either way
    if (t < limit) {
        if (ei[t] > 0xFFFFFFFFULL) atomicExch(&g_is32, 1);
    }
}

// ---------------------------------------------------------------------------
// 2. histogram of dst (scalar int atomics only)
// ---------------------------------------------------------------------------
__global__ void hist_kernel(const void* __restrict__ ei, int E) {
    int e = blockIdx.x * blockDim.x + threadIdx.x;
    if (e >= E) return;
    int d = read_idx(ei, E, 1, e, g_is32);
    atomicAdd(&g_count[d], 1);
}

// ---------------------------------------------------------------------------
// 3a. scan phase A: per-block reduction of counts -> g_partial[b]
// ---------------------------------------------------------------------------
__global__ void scanA_kernel() {
    __shared__ int sh[32];
    int i = blockIdx.x * SCAN_TPB + threadIdx.x;
    int v = (i < N_NODES) ? g_count[i] : 0;
    // warp reduce
    #pragma unroll
    for (int o = 16; o > 0; o >>= 1) v += __shfl_down_sync(0xFFFFFFFFu, v, o);
    int lane = threadIdx.x & 31, warp = threadIdx.x >> 5;
    if (lane == 0) sh[warp] = v;
    __syncthreads();
    if (warp == 0) {
        v = (lane < SCAN_TPB / 32) ? sh[lane] : 0;
        #pragma unroll
        for (int o = 16; o > 0; o >>= 1) v += __shfl_down_sync(0xFFFFFFFFu, v, o);
        if (lane == 0) g_partial[blockIdx.x] = v;
    }
}

// ---------------------------------------------------------------------------
// 3b. scan phase B: exclusive scan of the SCAN_NB partials (one tiny block)
// ---------------------------------------------------------------------------
__global__ void scanB_kernel() {
    __shared__ int sh[128];
    int t = threadIdx.x;                       // blockDim = 128 >= SCAN_NB
    int v = (t < SCAN_NB) ? g_partial[t] : 0;
    sh[t] = v;
    __syncthreads();
    for (int off = 1; off < 128; off <<= 1) {
        int u = (t >= off) ? sh[t - off] : 0;
        __syncthreads();
        sh[t] += u;
        __syncthreads();
    }
    if (t < SCAN_NB) g_partial[t] = sh[t] - v;           // exclusive
    if (t == 127) g_rowstart[N_NODES] = sh[127];          // total edges
}

// ---------------------------------------------------------------------------
// 3c. scan phase C: block-local exclusive scan + block offset;
//     fused rowstart + dinv writes.
// ---------------------------------------------------------------------------
__global__ void scanC_kernel() {
    __shared__ int sh[SCAN_TPB];
    int t = threadIdx.x;
    int i = blockIdx.x * SCAN_TPB + t;
    int c = (i < N_NODES) ? g_count[i] : 0;
    sh[t] = c;
    __syncthreads();
    for (int off = 1; off < SCAN_TPB; off <<= 1) {
        int u = (t >= off) ? sh[t - off] : 0;
        __syncthreads();
        sh[t] += u;
        __syncthreads();
    }
    if (i < N_NODES) {
        g_rowstart[i] = g_partial[blockIdx.x] + sh[t] - c;  // exclusive
        g_dinv[i] = rsqrtf((float)c + 1.0f);
    }
}

// ---------------------------------------------------------------------------
// 4. fill adjacency (src ids grouped by dst; order irrelevant)
// ---------------------------------------------------------------------------
__global__ void fill_kernel(const void* __restrict__ ei, int E) {
    int e = blockIdx.x * blockDim.x + threadIdx.x;
    if (e >= E) return;
    int is32 = g_is32;
    int sidx = read_idx(ei, E, 0, e, is32);
    int d    = read_idx(ei, E, 1, e, is32);
    int pos = atomicAdd(&g_cursor[d], 1);
    g_adj[g_rowstart[d] + pos] = sidx;
}

// ---------------------------------------------------------------------------
// 5. g_h = x @ W1   (N x 128) @ (128 x 64)
// ---------------------------------------------------------------------------
__global__ void gemm1_kernel(const float* __restrict__ x,
                             const float* __restrict__ W1) {
    __shared__ float Ws[F_IN * F_HID];   // 32 KB
    __shared__ float xs[16][F_IN];       // 8 KB

    int tid = threadIdx.x;               // 0..255
    for (int i = tid; i < F_IN * F_HID; i += 256) Ws[i] = W1[i];

    int row0 = blockIdx.x * 16;
    for (int i = tid; i < 16 * F_IN; i += 256) {
        int r = i >> 7, k = i & 127;
        int row = row0 + r;
        xs[r][k] = (row < N_NODES) ? x[(size_t)row * F_IN + k] : 0.0f;
    }
    __syncthreads();

    int col = tid & 63;
    int rg  = tid >> 6;
    float acc0 = 0.f, acc1 = 0.f, acc2 = 0.f, acc3 = 0.f;
    int rbase = rg * 4;
#pragma unroll
    for (int k = 0; k < F_IN; k++) {
        float w = Ws[k * F_HID + col];
        acc0 = fmaf(xs[rbase + 0][k], w, acc0);
        acc1 = fmaf(xs[rbase + 1][k], w, acc1);
        acc2 = fmaf(xs[rbase + 2][k], w, acc2);
        acc3 = fmaf(xs[rbase + 3][k], w, acc3);
    }
    int row = row0 + rbase;
    if (row + 0 < N_NODES) g_h[(size_t)(row + 0) * F_HID + col] = acc0;
    if (row + 1 < N_NODES) g_h[(size_t)(row + 1) * F_HID + col] = acc1;
    if (row + 2 < N_NODES) g_h[(size_t)(row + 2) * F_HID + col] = acc2;
    if (row + 3 < N_NODES) g_h[(size_t)(row + 3) * F_HID + col] = acc3;
}

// ---------------------------------------------------------------------------
// 6/7. aggregate: one warp per node. Lane l accumulates features 2l, 2l+1.
//      out[d] = sum_{s in adj(d)} dinv[s]*dinv[d]*in[s] + dinv[d]^2*in[d]
// ---------------------------------------------------------------------------
template <bool PASS1>
__global__ void agg_kernel(const float* __restrict__ b1) {
    const float* in  = PASS1 ? g_h  : g_h2;
    float*       out = PASS1 ? g_h2 : g_agg;

    int warp = threadIdx.x >> 5;
    int lane = threadIdx.x & 31;
    int node = blockIdx.x * 8 + warp;     // 256 threads = 8 warps
    if (node >= N_NODES) return;

    float di = g_dinv[node];
    float2 v = *reinterpret_cast<const float2*>(&in[(size_t)node * F_HID + lane * 2]);
    float accx = di * di * v.x;
    float accy = di * di * v.y;

    int beg = g_rowstart[node];
    int end = g_rowstart[node + 1];

    int j = beg;
    for (; j + 1 < end; j += 2) {
        int s0 = g_adj[j];
        int s1 = g_adj[j + 1];
        float c0 = g_dinv[s0] * di;
        float c1 = g_dinv[s1] * di;
        float2 h0 = *reinterpret_cast<const float2*>(&in[(size_t)s0 * F_HID + lane * 2]);
        float2 h1 = *reinterpret_cast<const float2*>(&in[(size_t)s1 * F_HID + lane * 2]);
        accx = fmaf(c0, h0.x, accx);
        accy = fmaf(c0, h0.y, accy);
        accx = fmaf(c1, h1.x, accx);
        accy = fmaf(c1, h1.y, accy);
    }
    if (j < end) {
        int s = g_adj[j];
        float c = g_dinv[s] * di;
        float2 hv = *reinterpret_cast<const float2*>(&in[(size_t)s * F_HID + lane * 2]);
        accx = fmaf(c, hv.x, accx);
        accy = fmaf(c, hv.y, accy);
    }

    if (PASS1) {
        accx += b1[lane * 2 + 0];
        accy += b1[lane * 2 + 1];
        accx = accx > 0.f ? accx : 0.f;
        accy = accy > 0.f ? accy : 0.f;
    }
    *reinterpret_cast<float2*>(&out[(size_t)node * F_HID + lane * 2]) =
        make_float2(accx, accy);
}

// ---------------------------------------------------------------------------
// 8. out GEMMs: mu = g_agg@W_mu + b_mu; ls = g_agg@W_ls + b_ls
// ---------------------------------------------------------------------------
__global__ void out_kernel(const float* __restrict__ Wmu,
                           const float* __restrict__ bmu,
                           const float* __restrict__ Wls,
                           const float* __restrict__ bls,
                           float* __restrict__ out) {
    __shared__ float Wm[F_HID * F_OUT];
    __shared__ float Wl[F_HID * F_OUT];
    __shared__ float hs[8][F_HID];

    int tid = threadIdx.x;  // 0..255
    for (int i = tid; i < F_HID * F_OUT; i += 256) { Wm[i] = Wmu[i]; Wl[i] = Wls[i]; }

    int node0 = blockIdx.x * 8;
    for (int i = tid; i < 8 * F_HID; i += 256) {
        int r = i >> 6, f = i & 63;
        int node = node0 + r;
        if (node < N_NODES) hs[r][f] = g_agg[(size_t)node * F_HID + f];
    }
    __syncthreads();

    int warp = tid >> 5, lane = tid & 31;
    int node = node0 + warp;
    if (node >= N_NODES) return;

    float am = bmu[lane];
    float al = bls[lane];
#pragma unroll
    for (int f = 0; f < F_HID; f++) {
        float hv = hs[warp][f];
        am = fmaf(hv, Wm[f * F_OUT + lane], am);
        al = fmaf(hv, Wl[f * F_OUT + lane], al);
    }
    out[(size_t)node * F_OUT + lane] = am;
    out[(size_t)N_NODES * F_OUT + (size_t)node * F_OUT + lane] = al;
}

// ---------------------------------------------------------------------------
// launch — everything on cudaStreamPerThread so graph capture records it
// ---------------------------------------------------------------------------
extern "C" void kernel_launch(void* const* d_in, const int* in_sizes, int n_in,
                              void* d_out, int out_size) {
    const float* x   = (const float*)d_in[0];
    const void*  ei  = d_in[1];                    // [2, E], int32 OR int64
    const float* W1  = (const float*)d_in[2];
    const float* b1  = (const float*)d_in[3];
    const float* Wmu = (const float*)d_in[4];
    const float* bmu = (const float*)d_in[5];
    const float* Wls = (const float*)d_in[6];
    const float* bls = (const float*)d_in[7];
    float*       out = (float*)d_out;

    const int E = in_sizes[1] / 2;
    const int T = 256;
    cudaStream_t s = cudaStreamPerThread;

    init_kernel<<<(N_NODES + T - 1) / T, T, 0, s>>>();
    detect_kernel<<<8, T, 0, s>>>((const unsigned long long*)ei, E);
    hist_kernel<<<(E + T - 1) / T, T, 0, s>>>(ei, E);
    scanA_kernel<<<SCAN_NB, SCAN_TPB, 0, s>>>();
    scanB_kernel<<<1, 128, 0, s>>>();
    scanC_kernel<<<SCAN_NB, SCAN_TPB, 0, s>>>();
    fill_kernel<<<(E + T - 1) / T, T, 0, s>>>(ei, E);
    gemm1_kernel<<<(N_NODES + 15) / 16, T, 0, s>>>(x, W1);
    agg_kernel<true ><<<(N_NODES + 7) / 8, T, 0, s>>>(b1);
    agg_kernel<false><<<(N_NODES + 7) / 8, T, 0, s>>>(b1);
    out_kernel<<<(N_NODES + 7) / 8, T, 0, s>>>(Wmu, bmu, Wls, bls, out);
}

// round 7
// speedup vs baseline: 1.5389x; 1.0385x over previous
#include <cuda_runtime.h>
#include <cstdint>

#define N_NODES 100000
#define E_MAX   1700000
#define F_IN    128
#define F_HID   64
#define F_OUT   32
#define SCAN_TPB 1024
#define SCAN_NB  ((N_NODES + SCAN_TPB - 1) / SCAN_TPB)   // 98

// Scratch (no allocations allowed). Referenced ONLY from device code.
__device__ float g_h[N_NODES * F_HID];     // h1 = x@W1
__device__ float g_h2[N_NODES * F_HID];    // relu(gcn1)
__device__ float g_agg[N_NODES * F_HID];   // hagg2 (pre-output-GEMM)
__device__ float g_dinv[N_NODES];          // 1/sqrt(deg)
__device__ int   g_count[N_NODES];         // in-degree (excl. self-loop)
__device__ int   g_cursor[N_NODES];        // fill cursors
__device__ int   g_rowstart[N_NODES + 1];  // CSR row offsets (by dst)
__device__ int   g_adj[E_MAX];             // src ids grouped by dst
__device__ int   g_partial[SCAN_NB];       // per-block sums for scan
__device__ int   g_is32;                   // 1 if edge_index is int32

// ---------------------------------------------------------------------------
// index readers (uniform branch on detected dtype)
// ---------------------------------------------------------------------------
__device__ __forceinline__ int read_idx(const void* ei, int E, int row, int e,
                                        int is32) {
    if (is32)  return ((const int*)ei)[(size_t)row * E + e];
    else       return (int)((const long long*)ei)[(size_t)row * E + e];
}

// ---------------------------------------------------------------------------
// 1. init: zero counts + cursors + dtype flag
// ---------------------------------------------------------------------------
__global__ void init_kernel() {
    int i = blockIdx.x * blockDim.x + threadIdx.x;
    if (i < N_NODES) { g_count[i] = 0; g_cursor[i] = 0; }
    if (i == 0) g_is32 = 0;
}

// ---------------------------------------------------------------------------
// 1b. dtype detect: int64 node ids (< 1e5) have zero high-32 in every word;
//     packed int32 pairs have nonzero high half whenever idx[2t+1] != 0.
// ---------------------------------------------------------------------------
__global__ void detect_kernel(const unsigned long long* __restrict__ ei, int E) {
    int t = blockIdx.x * blockDim.x + threadIdx.x;
    int limit = (E < 2048) ? E : 2048;   // words fully inside row 0 either way
    if (t < limit) {
        if (ei[t] > 0xFFFFFFFFULL) atomicExch(&g_is32, 1);
    }
}

// ---------------------------------------------------------------------------
// 2. histogram of dst (scalar int atomics only)
// ---------------------------------------------------------------------------
__global__ void hist_kernel(const void* __restrict__ ei, int E) {
    int e = blockIdx.x * blockDim.x + threadIdx.x;
    if (e >= E) return;
    int d = read_idx(ei, E, 1, e, g_is32);
    atomicAdd(&g_count[d], 1);
}

// ---------------------------------------------------------------------------
// 3a. scan phase A: per-block reduction of counts -> g_partial[b]
// ---------------------------------------------------------------------------
__global__ void scanA_kernel() {
    __shared__ int sh[32];
    int i = blockIdx.x * SCAN_TPB + threadIdx.x;
    int v = (i < N_NODES) ? g_count[i] : 0;
    #pragma unroll
    for (int o = 16; o > 0; o >>= 1) v += __shfl_down_sync(0xFFFFFFFFu, v, o);
    int lane = threadIdx.x & 31, warp = threadIdx.x >> 5;
    if (lane == 0) sh[warp] = v;
    __syncthreads();
    if (warp == 0) {
        v = (lane < SCAN_TPB / 32) ? sh[lane] : 0;
        #pragma unroll
        for (int o = 16; o > 0; o >>= 1) v += __shfl_down_sync(0xFFFFFFFFu, v, o);
        if (lane == 0) g_partial[blockIdx.x] = v;
    }
}

// ---------------------------------------------------------------------------
// 3b. scan phase B: exclusive scan of the SCAN_NB partials (one tiny block)
// ---------------------------------------------------------------------------
__global__ void scanB_kernel() {
    __shared__ int sh[128];
    int t = threadIdx.x;                       // blockDim = 128 >= SCAN_NB
    int v = (t < SCAN_NB) ? g_partial[t] : 0;
    sh[t] = v;
    __syncthreads();
    for (int off = 1; off < 128; off <<= 1) {
        int u = (t >= off) ? sh[t - off] : 0;
        __syncthreads();
        sh[t] += u;
        __syncthreads();
    }
    if (t < SCAN_NB) g_partial[t] = sh[t] - v;           // exclusive
    if (t == 127) g_rowstart[N_NODES] = sh[127];          // total edges
}

// ---------------------------------------------------------------------------
// 3c. scan phase C: block-local exclusive scan + block offset;
//     fused rowstart + dinv writes.
// ---------------------------------------------------------------------------
__global__ void scanC_kernel() {
    __shared__ int sh[SCAN_TPB];
    int t = threadIdx.x;
    int i = blockIdx.x * SCAN_TPB + t;
    int c = (i < N_NODES) ? g_count[i] : 0;
    sh[t] = c;
    __syncthreads();
    for (int off = 1; off < SCAN_TPB; off <<= 1) {
        int u = (t >= off) ? sh[t - off] : 0;
        __syncthreads();
        sh[t] += u;
        __syncthreads();
    }
    if (i < N_NODES) {
        g_rowstart[i] = g_partial[blockIdx.x] + sh[t] - c;  // exclusive
        g_dinv[i] = rsqrtf((float)c + 1.0f);
    }
}

// ---------------------------------------------------------------------------
// 4. fill adjacency (src ids grouped by dst; order irrelevant)
// ---------------------------------------------------------------------------
__global__ void fill_kernel(const void* __restrict__ ei, int E) {
    int e = blockIdx.x * blockDim.x + threadIdx.x;
    if (e >= E) return;
    int is32 = g_is32;
    int sidx = read_idx(ei, E, 0, e, is32);
    int d    = read_idx(ei, E, 1, e, is32);
    int pos = atomicAdd(&g_cursor[d], 1);
    g_adj[g_rowstart[d] + pos] = sidx;
}

// ---------------------------------------------------------------------------
// 5. g_h = x @ W1   (N x 128) @ (128 x 64); 32 rows/block, 256 threads.
//    Thread (col = tid&63, rg = tid>>6) computes 8 rows of one column.
// ---------------------------------------------------------------------------
__global__ void gemm1_kernel(const float* __restrict__ x,
                             const float* __restrict__ W1) {
    __shared__ float Ws[F_IN * F_HID];   // 32 KB
    __shared__ float xs[32][F_IN];       // 16 KB

    int tid = threadIdx.x;               // 0..255
    for (int i = tid; i < F_IN * F_HID; i += 256) Ws[i] = W1[i];

    int row0 = blockIdx.x * 32;
    for (int i = tid; i < 32 * F_IN; i += 256) {
        int r = i >> 7, k = i & 127;
        int row = row0 + r;
        xs[r][k] = (row < N_NODES) ? x[(size_t)row * F_IN + k] : 0.0f;
    }
    __syncthreads();

    int col = tid & 63;
    int rg  = tid >> 6;                  // 0..3 -> rows rg*8 .. rg*8+7
    int rbase = rg * 8;
    float acc[8];
    #pragma unroll
    for (int r = 0; r < 8; r++) acc[r] = 0.0f;

#pragma unroll
    for (int k = 0; k < F_IN; k++) {
        float w = Ws[k * F_HID + col];
        #pragma unroll
        for (int r = 0; r < 8; r++) acc[r] = fmaf(xs[rbase + r][k], w, acc[r]);
    }
    #pragma unroll
    for (int r = 0; r < 8; r++) {
        int row = row0 + rbase + r;
        if (row < N_NODES) g_h[(size_t)row * F_HID + col] = acc[r];
    }
}

// ---------------------------------------------------------------------------
// 6/7. aggregate: 16 lanes per node (each lane owns 4 features via float4),
//      2 nodes per warp, edge loop unrolled x4 for MLP.
//      out[d] = sum_{s in adj(d)} dinv[s]*dinv[d]*in[s] + dinv[d]^2*in[d]
// ---------------------------------------------------------------------------
template <bool PASS1>
__global__ void agg_kernel(const float* __restrict__ b1) {
    const float* in  = PASS1 ? g_h  : g_h2;
    float*       out = PASS1 ? g_h2 : g_agg;

    int tid    = threadIdx.x;            // 256 threads = 16 nodes/block
    int group  = tid >> 4;               // 0..15: node slot in block
    int lane16 = tid & 15;               // feature chunk owner
    int node = blockIdx.x * 16 + group;
    if (node >= N_NODES) return;

    int fo = lane16 * 4;                 // feature offset (float4)
    float di = g_dinv[node];

    float4 v = *reinterpret_cast<const float4*>(&in[(size_t)node * F_HID + fo]);
    float dd = di * di;
    float ax = dd * v.x, ay = dd * v.y, az = dd * v.z, aw = dd * v.w;

    int beg = g_rowstart[node];
    int end = g_rowstart[node + 1];

    int j = beg;
    for (; j + 3 < end; j += 4) {
        int s0 = g_adj[j + 0];
        int s1 = g_adj[j + 1];
        int s2 = g_adj[j + 2];
        int s3 = g_adj[j + 3];
        float c0 = g_dinv[s0] * di;
        float c1 = g_dinv[s1] * di;
        float c2 = g_dinv[s2] * di;
        float c3 = g_dinv[s3] * di;
        float4 h0 = *reinterpret_cast<const float4*>(&in[(size_t)s0 * F_HID + fo]);
        float4 h1 = *reinterpret_cast<const float4*>(&in[(size_t)s1 * F_HID + fo]);
        float4 h2 = *reinterpret_cast<const float4*>(&in[(size_t)s2 * F_HID + fo]);
        float4 h3 = *reinterpret_cast<const float4*>(&in[(size_t)s3 * F_HID + fo]);
        ax = fmaf(c0, h0.x, ax); ay = fmaf(c0, h0.y, ay);
        az = fmaf(c0, h0.z, az); aw = fmaf(c0, h0.w, aw);
        ax = fmaf(c1, h1.x, ax); ay = fmaf(c1, h1.y, ay);
        az = fmaf(c1, h1.z, az); aw = fmaf(c1, h1.w, aw);
        ax = fmaf(c2, h2.x, ax); ay = fmaf(c2, h2.y, ay);
        az = fmaf(c2, h2.z, az); aw = fmaf(c2, h2.w, aw);
        ax = fmaf(c3, h3.x, ax); ay = fmaf(c3, h3.y, ay);
        az = fmaf(c3, h3.z, az); aw = fmaf(c3, h3.w, aw);
    }
    for (; j < end; j++) {
        int s = g_adj[j];
        float c = g_dinv[s] * di;
        float4 hv = *reinterpret_cast<const float4*>(&in[(size_t)s * F_HID + fo]);
        ax = fmaf(c, hv.x, ax); ay = fmaf(c, hv.y, ay);
        az = fmaf(c, hv.z, az); aw = fmaf(c, hv.w, aw);
    }

    if (PASS1) {
        float4 bb = *reinterpret_cast<const float4*>(&b1[fo]);
        ax += bb.x; ay += bb.y; az += bb.z; aw += bb.w;
        ax = ax > 0.f ? ax : 0.f;
        ay = ay > 0.f ? ay : 0.f;
        az = az > 0.f ? az : 0.f;
        aw = aw > 0.f ? aw : 0.f;
    }
    *reinterpret_cast<float4*>(&out[(size_t)node * F_HID + fo]) =
        make_float4(ax, ay, az, aw);
}

// ---------------------------------------------------------------------------
// 8. out GEMMs: mu = g_agg@W_mu + b_mu; ls = g_agg@W_ls + b_ls
// ---------------------------------------------------------------------------
__global__ void out_kernel(const float* __restrict__ Wmu,
                           const float* __restrict__ bmu,
                           const float* __restrict__ Wls,
                           const float* __restrict__ bls,
                           float* __restrict__ out) {
    __shared__ float Wm[F_HID * F_OUT];
    __shared__ float Wl[F_HID * F_OUT];
    __shared__ float hs[8][F_HID];

    int tid = threadIdx.x;  // 0..255
    for (int i = tid; i < F_HID * F_OUT; i += 256) { Wm[i] = Wmu[i]; Wl[i] = Wls[i]; }

    int node0 = blockIdx.x * 8;
    for (int i = tid; i < 8 * F_HID; i += 256) {
        int r = i >> 6, f = i & 63;
        int node = node0 + r;
        if (node < N_NODES) hs[r][f] = g_agg[(size_t)node * F_HID + f];
    }
    __syncthreads();

    int warp = tid >> 5, lane = tid & 31;
    int node = node0 + warp;
    if (node >= N_NODES) return;

    float am = bmu[lane];
    float al = bls[lane];
#pragma unroll
    for (int f = 0; f < F_HID; f++) {
        float hv = hs[warp][f];
        am = fmaf(hv, Wm[f * F_OUT + lane], am);
        al = fmaf(hv, Wl[f * F_OUT + lane], al);
    }
    out[(size_t)node * F_OUT + lane] = am;
    out[(size_t)N_NODES * F_OUT + (size_t)node * F_OUT + lane] = al;
}

// ---------------------------------------------------------------------------
// launch — everything on cudaStreamPerThread so graph capture records it
// ---------------------------------------------------------------------------
extern "C" void kernel_launch(void* const* d_in, const int* in_sizes, int n_in,
                              void* d_out, int out_size) {
    const float* x   = (const float*)d_in[0];
    const void*  ei  = d_in[1];                    // [2, E], int32 OR int64
    const float* W1  = (const float*)d_in[2];
    const float* b1  = (const float*)d_in[3];
    const float* Wmu = (const float*)d_in[4];
    const float* bmu = (const float*)d_in[5];
    const float* Wls = (const float*)d_in[6];
    const float* bls = (const float*)d_in[7];
    float*       out = (float*)d_out;

    const int E = in_sizes[1] / 2;
    const int T = 256;
    cudaStream_t s = cudaStreamPerThread;

    init_kernel<<<(N_NODES + T - 1) / T, T, 0, s>>>();
    detect_kernel<<<8, T, 0, s>>>((const unsigned long long*)ei, E);
    hist_kernel<<<(E + T - 1) / T, T, 0, s>>>(ei, E);
    scanA_kernel<<<SCAN_NB, SCAN_TPB, 0, s>>>();
    scanB_kernel<<<1, 128, 0, s>>>();
    scanC_kernel<<<SCAN_NB, SCAN_TPB, 0, s>>>();
    fill_kernel<<<(E + T - 1) / T, T, 0, s>>>(ei, E);
    gemm1_kernel<<<(N_NODES + 31) / 32, T, 0, s>>>(x, W1);
    agg_kernel<true ><<<(N_NODES + 15) / 16, T, 0, s>>>(b1);
    agg_kernel<false><<<(N_NODES + 15) / 16, T, 0, s>>>(b1);
    out_kernel<<<(N_NODES + 7) / 8, T, 0, s>>>(Wmu, bmu, Wls, bls, out);
}

// round 8
// speedup vs baseline: 1.6455x; 1.0693x over previous
#include <cuda_runtime.h>
#include <cstdint>

#define N_NODES 100000
#define E_MAX   1700000
#define F_IN    128
#define F_HID   64
#define F_OUT   32
#define SCAN_TPB 1024
#define SCAN_NB  ((N_NODES + SCAN_TPB - 1) / SCAN_TPB)   // 98

// Scratch (no allocations allowed). Referenced ONLY from device code.
__device__ float g_h[N_NODES * F_HID];     // h1 = x@W1
__device__ float g_h2[N_NODES * F_HID];    // relu(gcn1)
__device__ float g_dinv[N_NODES];          // 1/sqrt(deg)
__device__ int   g_count[N_NODES];         // in-degree (excl. self-loop)
__device__ int   g_cursor[N_NODES];        // fill cursors
__device__ int   g_rowstart[N_NODES + 1];  // CSR row offsets (by dst)
__device__ int   g_adj[E_MAX];             // src ids grouped by dst
__device__ int   g_partial[SCAN_NB];       // per-block sums for scan
__device__ int   g_is32;                   // 1 if edge_index is int32

// ---------------------------------------------------------------------------
// index readers (uniform branch on detected dtype)
// ---------------------------------------------------------------------------
__device__ __forceinline__ int read_idx(const void* ei, int E, int row, int e,
                                        int is32) {
    if (is32)  return ((const int*)ei)[(size_t)row * E + e];
    else       return (int)((const long long*)ei)[(size_t)row * E + e];
}

// ---------------------------------------------------------------------------
// 1. init: zero counts + cursors + dtype flag
// ---------------------------------------------------------------------------
__global__ void init_kernel() {
    int i = blockIdx.x * blockDim.x + threadIdx.x;
    if (i < N_NODES) { g_count[i] = 0; g_cursor[i] = 0; }
    if (i == 0) g_is32 = 0;
}

// ---------------------------------------------------------------------------
// 1b. dtype detect: int64 node ids (< 1e5) have zero high-32 in every word;
//     packed int32 pairs have nonzero high half whenever idx[2t+1] != 0.
// ---------------------------------------------------------------------------
__global__ void detect_kernel(const unsigned long long* __restrict__ ei, int E) {
    int t = blockIdx.x * blockDim.x + threadIdx.x;
    int limit = (E < 2048) ? E : 2048;   // words fully inside row 0 either way
    if (t < limit) {
        if (ei[t] > 0xFFFFFFFFULL) atomicExch(&g_is32, 1);
    }
}

// ---------------------------------------------------------------------------
// 2. histogram of dst (scalar int atomics only)
// ---------------------------------------------------------------------------
__global__ void hist_kernel(const void* __restrict__ ei, int E) {
    int e = blockIdx.x * blockDim.x + threadIdx.x;
    if (e >= E) return;
    int d = read_idx(ei, E, 1, e, g_is32);
    atomicAdd(&g_count[d], 1);
}

// ---------------------------------------------------------------------------
// 3a. scan phase A: per-block reduction of counts -> g_partial[b]
// ---------------------------------------------------------------------------
__global__ void scanA_kernel() {
    __shared__ int sh[32];
    int i = blockIdx.x * SCAN_TPB + threadIdx.x;
    int v = (i < N_NODES) ? g_count[i] : 0;
    #pragma unroll
    for (int o = 16; o > 0; o >>= 1) v += __shfl_down_sync(0xFFFFFFFFu, v, o);
    int lane = threadIdx.x & 31, warp = threadIdx.x >> 5;
    if (lane == 0) sh[warp] = v;
    __syncthreads();
    if (warp == 0) {
        v = (lane < SCAN_TPB / 32) ? sh[lane] : 0;
        #pragma unroll
        for (int o = 16; o > 0; o >>= 1) v += __shfl_down_sync(0xFFFFFFFFu, v, o);
        if (lane == 0) g_partial[blockIdx.x] = v;
    }
}

// ---------------------------------------------------------------------------
// 3b. scan phase B: exclusive scan of the SCAN_NB partials (one tiny block)
// ---------------------------------------------------------------------------
__global__ void scanB_kernel() {
    __shared__ int sh[128];
    int t = threadIdx.x;                       // blockDim = 128 >= SCAN_NB
    int v = (t < SCAN_NB) ? g_partial[t] : 0;
    sh[t] = v;
    __syncthreads();
    for (int off = 1; off < 128; off <<= 1) {
        int u = (t >= off) ? sh[t - off] : 0;
        __syncthreads();
        sh[t] += u;
        __syncthreads();
    }
    if (t < SCAN_NB) g_partial[t] = sh[t] - v;           // exclusive
    if (t == 127) g_rowstart[N_NODES] = sh[127];          // total edges
}

// ---------------------------------------------------------------------------
// 3c. scan phase C: block-local exclusive scan + block offset;
//     fused rowstart + dinv writes.
// ---------------------------------------------------------------------------
__global__ void scanC_kernel() {
    __shared__ int sh[SCAN_TPB];
    int t = threadIdx.x;
    int i = blockIdx.x * SCAN_TPB + t;
    int c = (i < N_NODES) ? g_count[i] : 0;
    sh[t] = c;
    __syncthreads();
    for (int off = 1; off < SCAN_TPB; off <<= 1) {
        int u = (t >= off) ? sh[t - off] : 0;
        __syncthreads();
        sh[t] += u;
        __syncthreads();
    }
    if (i < N_NODES) {
        g_rowstart[i] = g_partial[blockIdx.x] + sh[t] - c;  // exclusive
        g_dinv[i] = rsqrtf((float)c + 1.0f);
    }
}

// ---------------------------------------------------------------------------
// 4. fill adjacency (src ids grouped by dst; order irrelevant)
// ---------------------------------------------------------------------------
__global__ void fill_kernel(const void* __restrict__ ei, int E) {
    int e = blockIdx.x * blockDim.x + threadIdx.x;
    if (e >= E) return;
    int is32 = g_is32;
    int sidx = read_idx(ei, E, 0, e, is32);
    int d    = read_idx(ei, E, 1, e, is32);
    int pos = atomicAdd(&g_cursor[d], 1);
    g_adj[g_rowstart[d] + pos] = sidx;
}

// ---------------------------------------------------------------------------
// 5. g_h = x @ W1   (N x 128) @ (128 x 64); 32 rows/block, 256 threads.
// ---------------------------------------------------------------------------
__global__ void gemm1_kernel(const float* __restrict__ x,
                             const float* __restrict__ W1) {
    __shared__ float Ws[F_IN * F_HID];   // 32 KB
    __shared__ float xs[32][F_IN];       // 16 KB

    int tid = threadIdx.x;               // 0..255
    for (int i = tid; i < F_IN * F_HID; i += 256) Ws[i] = W1[i];

    int row0 = blockIdx.x * 32;
    for (int i = tid; i < 32 * F_IN; i += 256) {
        int r = i >> 7, k = i & 127;
        int row = row0 + r;
        xs[r][k] = (row < N_NODES) ? x[(size_t)row * F_IN + k] : 0.0f;
    }
    __syncthreads();

    int col = tid & 63;
    int rg  = tid >> 6;                  // 0..3 -> rows rg*8 .. rg*8+7
    int rbase = rg * 8;
    float acc[8];
    #pragma unroll
    for (int r = 0; r < 8; r++) acc[r] = 0.0f;

#pragma unroll
    for (int k = 0; k < F_IN; k++) {
        float w = Ws[k * F_HID + col];
        #pragma unroll
        for (int r = 0; r < 8; r++) acc[r] = fmaf(xs[rbase + r][k], w, acc[r]);
    }
    #pragma unroll
    for (int r = 0; r < 8; r++) {
        int row = row0 + rbase + r;
        if (row < N_NODES) g_h[(size_t)row * F_HID + col] = acc[r];
    }
}

// ---------------------------------------------------------------------------
// shared aggregation core: 16 lanes per node, lane owns 4 features (float4),
// edge loop unrolled x4. Returns accumulated float4 for (node, fo).
// ---------------------------------------------------------------------------
__device__ __forceinline__ float4 agg_node(const float* __restrict__ in,
                                           int node, int fo) {
    float di = g_dinv[node];
    float4 v = *reinterpret_cast<const float4*>(&in[(size_t)node * F_HID + fo]);
    float dd = di * di;
    float ax = dd * v.x, ay = dd * v.y, az = dd * v.z, aw = dd * v.w;

    int beg = g_rowstart[node];
    int end = g_rowstart[node + 1];

    int j = beg;
    for (; j + 3 < end; j += 4) {
        int s0 = g_adj[j + 0];
        int s1 = g_adj[j + 1];
        int s2 = g_adj[j + 2];
        int s3 = g_adj[j + 3];
        float c0 = g_dinv[s0] * di;
        float c1 = g_dinv[s1] * di;
        float c2 = g_dinv[s2] * di;
        float c3 = g_dinv[s3] * di;
        float4 h0 = *reinterpret_cast<const float4*>(&in[(size_t)s0 * F_HID + fo]);
        float4 h1 = *reinterpret_cast<const float4*>(&in[(size_t)s1 * F_HID + fo]);
        float4 h2 = *reinterpret_cast<const float4*>(&in[(size_t)s2 * F_HID + fo]);
        float4 h3 = *reinterpret_cast<const float4*>(&in[(size_t)s3 * F_HID + fo]);
        ax = fmaf(c0, h0.x, ax); ay = fmaf(c0, h0.y, ay);
        az = fmaf(c0, h0.z, az); aw = fmaf(c0, h0.w, aw);
        ax = fmaf(c1, h1.x, ax); ay = fmaf(c1, h1.y, ay);
        az = fmaf(c1, h1.z, az); aw = fmaf(c1, h1.w, aw);
        ax = fmaf(c2, h2.x, ax); ay = fmaf(c2, h2.y, ay);
        az = fmaf(c2, h2.z, az); aw = fmaf(c2, h2.w, aw);
        ax = fmaf(c3, h3.x, ax); ay = fmaf(c3, h3.y, ay);
        az = fmaf(c3, h3.z, az); aw = fmaf(c3, h3.w, aw);
    }
    for (; j < end; j++) {
        int s = g_adj[j];
        float c = g_dinv[s] * di;
        float4 hv = *reinterpret_cast<const float4*>(&in[(size_t)s * F_HID + fo]);
        ax = fmaf(c, hv.x, ax); ay = fmaf(c, hv.y, ay);
        az = fmaf(c, hv.z, az); aw = fmaf(c, hv.w, aw);
    }
    return make_float4(ax, ay, az, aw);
}

// ---------------------------------------------------------------------------
// 6. pass-1 aggregate + bias + relu -> g_h2
// ---------------------------------------------------------------------------
__global__ void agg1_kernel(const float* __restrict__ b1) {
    int tid    = threadIdx.x;            // 256 threads = 16 nodes/block
    int group  = tid >> 4;
    int lane16 = tid & 15;
    int node = blockIdx.x * 16 + group;
    if (node >= N_NODES) return;

    int fo = lane16 * 4;
    float4 a = agg_node(g_h, node, fo);

    float4 bb = *reinterpret_cast<const float4*>(&b1[fo]);
    a.x += bb.x; a.y += bb.y; a.z += bb.z; a.w += bb.w;
    a.x = a.x > 0.f ? a.x : 0.f;
    a.y = a.y > 0.f ? a.y : 0.f;
    a.z = a.z > 0.f ? a.z : 0.f;
    a.w = a.w > 0.f ? a.w : 0.f;
    *reinterpret_cast<float4*>(&g_h2[(size_t)node * F_HID + fo]) = a;
}

// ---------------------------------------------------------------------------
// 7. FUSED pass-2 aggregate + dual output GEMM.
//    Phase A: aggregate 16 nodes into smem (registers -> hs).
//    Phase B: 8 warps x 2 nodes each: mu/logstd = hs @ W + b.
// ---------------------------------------------------------------------------
__global__ void agg2_out_kernel(const float* __restrict__ Wmu,
                                const float* __restrict__ bmu,
                                const float* __restrict__ Wls,
                                const float* __restrict__ bls,
                                float* __restrict__ out) {
    __shared__ float Wm[F_HID * F_OUT];  // 8 KB
    __shared__ float Wl[F_HID * F_OUT];  // 8 KB
    __shared__ float hs[16][F_HID];      // 4 KB

    int tid = threadIdx.x;               // 0..255
    for (int i = tid; i < F_HID * F_OUT; i += 256) { Wm[i] = Wmu[i]; Wl[i] = Wls[i]; }

    int node0 = blockIdx.x * 16;

    // Phase A: aggregation (16 lanes per node, float4 per lane)
    {
        int group  = tid >> 4;
        int lane16 = tid & 15;
        int node = node0 + group;
        if (node < N_NODES) {
            int fo = lane16 * 4;
            float4 a = agg_node(g_h2, node, fo);
            *reinterpret_cast<float4*>(&hs[group][fo]) = a;
        }
    }
    __syncthreads();

    // Phase B: dual GEMM, warp per node (2 nodes per warp via stride-8 loop)
    int warp = tid >> 5, lane = tid & 31;
    float bm = bmu[lane];
    float bl = bls[lane];
    #pragma unroll
    for (int nn = warp; nn < 16; nn += 8) {
        int node = node0 + nn;
        if (node >= N_NODES) continue;
        float am = bm;
        float al = bl;
        #pragma unroll
        for (int f = 0; f < F_HID; f++) {
            float hv = hs[nn][f];
            am = fmaf(hv, Wm[f * F_OUT + lane], am);
            al = fmaf(hv, Wl[f * F_OUT + lane], al);
        }
        out[(size_t)node * F_OUT + lane] = am;
        out[(size_t)N_NODES * F_OUT + (size_t)node * F_OUT + lane] = al;
    }
}

// ---------------------------------------------------------------------------
// launch — everything on cudaStreamPerThread so graph capture records it
// ---------------------------------------------------------------------------
extern "C" void kernel_launch(void* const* d_in, const int* in_sizes, int n_in,
                              void* d_out, int out_size) {
    const float* x   = (const float*)d_in[0];
    const void*  ei  = d_in[1];                    // [2, E], int32 OR int64
    const float* W1  = (const float*)d_in[2];
    const float* b1  = (const float*)d_in[3];
    const float* Wmu = (const float*)d_in[4];
    const float* bmu = (const float*)d_in[5];
    const float* Wls = (const float*)d_in[6];
    const float* bls = (const float*)d_in[7];
    float*       out = (float*)d_out;

    const int E = in_sizes[1] / 2;
    const int T = 256;
    cudaStream_t s = cudaStreamPerThread;

    init_kernel<<<(N_NODES + T - 1) / T, T, 0, s>>>();
    detect_kernel<<<8, T, 0, s>>>((const unsigned long long*)ei, E);
    hist_kernel<<<(E + T - 1) / T, T, 0, s>>>(ei, E);
    scanA_kernel<<<SCAN_NB, SCAN_TPB, 0, s>>>();
    scanB_kernel<<<1, 128, 0, s>>>();
    scanC_kernel<<<SCAN_NB, SCAN_TPB, 0, s>>>();
    fill_kernel<<<(E + T - 1) / T, T, 0, s>>>(ei, E);
    gemm1_kernel<<<(N_NODES + 31) / 32, T, 0, s>>>(x, W1);
    agg1_kernel<<<(N_NODES + 15) / 16, T, 0, s>>>(b1);
    agg2_out_kernel<<<(N_NODES + 15) / 16, T, 0, s>>>(Wmu, bmu, Wls, bls, out);
}